// round 10
// baseline (speedup 1.0000x reference)
#include <cuda_runtime.h>
#include <math.h>
#include <stdint.h>

#define N_NODES 50000
#define N_EDGES 800000
#define IN_CH   128
#define OUT_CH  64
#define BN_EPS  1e-5f

// ---------------- scratch (no allocation allowed) ----------------
__device__ float g_h[N_NODES * OUT_CH];      // x @ W
__device__ float g_agg[N_NODES * OUT_CH];    // aggregated messages (edges only)
__device__ int   g_deg[N_NODES];
__device__ float g_dinv[N_NODES];
__device__ float g_sum[OUT_CH];
__device__ float g_sumsq[OUT_CH];
__device__ int   g_eidx[2 * N_EDGES];        // decoded int32 edges (src then dst)
__device__ int   g_is64;
__device__ int   g_count;                    // act_bn grid-sync counter
__device__ volatile int g_flag;              // act_bn grid-sync flag

// ---------------- packed f32x2 FFMA ----------------
__device__ __forceinline__ void ffma2(uint64_t& d, uint64_t a, uint64_t b) {
    asm("fma.rn.f32x2 %0, %1, %2, %0;" : "+l"(d) : "l"(a), "l"(b));
}
union F4U2 { float4 f; struct { uint64_t lo, hi; } u; };
union U2F2 { uint64_t u; struct { float lo, hi; } f; };

// ---------------- fused init + dtype sniff + sync reset ----------------
// int64 edges (values < 50000) have every odd 32-bit word zero.
__global__ void k_init_sniff(const unsigned int* __restrict__ w) {
    int i = blockIdx.x * blockDim.x + threadIdx.x;
    if (i < N_NODES) g_deg[i] = 1;                 // self loop
    if (i < OUT_CH) { g_sum[i] = 0.f; g_sumsq[i] = 0.f; }
    if (i == 0) {
        g_count = 0; g_flag = 0;
        int odd_zero = 1;
        #pragma unroll
        for (int j = 0; j < 16; j++)
            if (w[2 * j + 1] != 0u) odd_zero = 0;
        g_is64 = odd_zero;
    }
}

// ---------------- fused decode + in-degree ----------------
__global__ void k_decode_deg(const unsigned int* __restrict__ w) {
    int i = blockIdx.x * blockDim.x + threadIdx.x;
    if (i >= 2 * N_EDGES) return;
    int is64 = g_is64;
    int v = (int)(is64 ? w[2 * (size_t)i] : w[i]);
    g_eidx[i] = v;
    if (i >= N_EDGES) atomicAdd(&g_deg[v], 1);     // dst half
}

__global__ void k_dinv() {
    int i = blockIdx.x * blockDim.x + threadIdx.x;
    if (i < N_NODES) g_dinv[i] = rsqrtf((float)g_deg[i]);
}

// ---------------- GEMM: h[N,64] = x[N,128] @ W[128,64], FFMA2 ----------------
// 64-row tile, 256 threads, 4 rows x 4 cols per thread (cols as 2 f32x2 pairs).
// A stored duplicated ({v,v} per element) so the broadcast operand is one LDS.64.
// Also zeroes g_agg rows (scatter accumulates into it later).
#define TILE_M 64
#define SMEM_A_FLOATS (TILE_M * IN_CH * 2)            /* 16384 floats = 64 KB */
#define SMEM_TOT ((SMEM_A_FLOATS + IN_CH * OUT_CH) * 4)  /* + Ws 32 KB = 96 KB */

__global__ void __launch_bounds__(256) k_gemm(const float* __restrict__ x,
                                              const float* __restrict__ W) {
    extern __shared__ float sm[];
    float* As2 = sm;                       // [64][128][2] duplicated
    float* Ws  = sm + SMEM_A_FLOATS;       // [128][64]
    const int tid  = threadIdx.x;
    const int row0 = blockIdx.x * TILE_M;

    // load W (8192 floats) as float4
    for (int i = tid; i < (IN_CH * OUT_CH) / 4; i += 256)
        ((float4*)Ws)[i] = ((const float4*)W)[i];

    // load x tile (64 x 128) as float4; store duplicated; zero-fill OOB rows
    for (int i = tid; i < (TILE_M * IN_CH) / 4; i += 256) {
        int lin = i * 4;
        int r = lin >> 7, c = lin & 127;
        int gr = row0 + r;
        float4 v = make_float4(0.f, 0.f, 0.f, 0.f);
        if (gr < N_NODES) v = *((const float4*)(x + (size_t)gr * IN_CH + c));
        float* p = As2 + ((size_t)r * IN_CH + c) * 2;
        *((float4*)p)     = make_float4(v.x, v.x, v.y, v.y);
        *((float4*)(p+4)) = make_float4(v.z, v.z, v.w, v.w);
    }
    __syncthreads();

    const int ty = tid >> 4;       // 0..15 -> rows ty*4..ty*4+3
    const int tx = tid & 15;       // 0..15 -> cols tx*4..tx*4+3
    uint64_t acc[4][2] = {};       // 4 rows x (2 f32x2 col-pairs)

    const float* pa0 = As2 + (ty * 4 + 0) * (IN_CH * 2);
    const float* pa1 = As2 + (ty * 4 + 1) * (IN_CH * 2);
    const float* pa2 = As2 + (ty * 4 + 2) * (IN_CH * 2);
    const float* pa3 = As2 + (ty * 4 + 3) * (IN_CH * 2);
    const float* pb  = Ws + tx * 4;

    #pragma unroll 4
    for (int k = 0; k < IN_CH; k++) {
        uint64_t a0 = *(const uint64_t*)(pa0 + 2 * k);
        uint64_t a1 = *(const uint64_t*)(pa1 + 2 * k);
        uint64_t a2 = *(const uint64_t*)(pa2 + 2 * k);
        uint64_t a3 = *(const uint64_t*)(pa3 + 2 * k);
        F4U2 b; b.f = *(const float4*)(pb + k * OUT_CH);
        ffma2(acc[0][0], a0, b.u.lo); ffma2(acc[0][1], a0, b.u.hi);
        ffma2(acc[1][0], a1, b.u.lo); ffma2(acc[1][1], a1, b.u.hi);
        ffma2(acc[2][0], a2, b.u.lo); ffma2(acc[2][1], a2, b.u.hi);
        ffma2(acc[3][0], a3, b.u.lo); ffma2(acc[3][1], a3, b.u.hi);
    }

    const float4 z = make_float4(0.f, 0.f, 0.f, 0.f);
    #pragma unroll
    for (int i = 0; i < 4; i++) {
        int r = row0 + ty * 4 + i;
        if (r < N_NODES) {
            U2F2 lo, hi; lo.u = acc[i][0]; hi.u = acc[i][1];
            *((float4*)&g_h[(size_t)r * OUT_CH + tx * 4]) =
                make_float4(lo.f.lo, lo.f.hi, hi.f.lo, hi.f.hi);
            *((float4*)&g_agg[(size_t)r * OUT_CH + tx * 4]) = z;
        }
    }
}

// ---------------- edge scatter: 16 threads / edge, v4 red ----------------
__global__ void __launch_bounds__(256) k_scatter() {
    long long t = (long long)blockIdx.x * blockDim.x + threadIdx.x;
    if (t >= (long long)N_EDGES * 16) return;
    int e = (int)(t >> 4), q = (int)(t & 15);
    int s = g_eidx[e];
    int d = g_eidx[N_EDGES + e];
    float norm = g_dinv[s] * g_dinv[d];
    float4 v = *((const float4*)&g_h[(size_t)s * OUT_CH + q * 4]);
    float* p = &g_agg[(size_t)d * OUT_CH + q * 4];
    asm volatile("red.global.add.v4.f32 [%0], {%1,%2,%3,%4};"
                 :: "l"(p), "f"(v.x * norm), "f"(v.y * norm),
                    "f"(v.z * norm), "f"(v.w * norm)
                 : "memory");
}

// ---- fused act + batchnorm, persistent grid with counter/flag sync ----
// out = BN(tanh(agg + dinv^2*h + bias)); values held in registers between phases.
// Grid = 296 (2 blocks/SM guaranteed resident -> spin is deadlock-free).
#define AB_GRID 296
#define AB_STRIDE (AB_GRID * 256)          /* 75776, multiple of 16 */
#define AB_ITERS 11                        /* ceil(800000 / 75776) */

__global__ void __launch_bounds__(256, 2) k_act_bn(const float* __restrict__ bias,
                                                   const float* __restrict__ gamma,
                                                   const float* __restrict__ beta,
                                                   float* __restrict__ out) {
    const int tid = threadIdx.x;
    const int cg = tid & 15;
    const float4 b4 = ((const float4*)bias)[cg];
    const int total4 = N_NODES * 16;
    const int base = blockIdx.x * 256 + tid;

    float4 vals[AB_ITERS];
    float4 s  = make_float4(0.f, 0.f, 0.f, 0.f);
    float4 s2 = make_float4(0.f, 0.f, 0.f, 0.f);

    // phase 1: tanh + stats, values cached in registers
    {
        int i = base;
        #pragma unroll
        for (int j = 0; j < AB_ITERS; j++, i += AB_STRIDE) {
            if (i < total4) {
                int n = i >> 4;
                float di = g_dinv[n];
                float sl = di * di;
                float4 a = ((const float4*)g_agg)[i];
                float4 h = ((const float4*)g_h)[i];
                float4 v;
                v.x = tanhf(a.x + sl * h.x + b4.x);
                v.y = tanhf(a.y + sl * h.y + b4.y);
                v.z = tanhf(a.z + sl * h.z + b4.z);
                v.w = tanhf(a.w + sl * h.w + b4.w);
                vals[j] = v;
                s.x += v.x; s.y += v.y; s.z += v.z; s.w += v.w;
                s2.x += v.x * v.x; s2.y += v.y * v.y; s2.z += v.z * v.z; s2.w += v.w * v.w;
            }
        }
    }

    // block reduce + global atomics
    __shared__ float4 sh[256];
    sh[tid] = s; __syncthreads();
    if (tid < 16) {
        float4 acc = sh[tid];
        #pragma unroll
        for (int j = 1; j < 16; j++) {
            float4 o = sh[tid + 16 * j];
            acc.x += o.x; acc.y += o.y; acc.z += o.z; acc.w += o.w;
        }
        atomicAdd(&g_sum[cg * 4 + 0], acc.x);
        atomicAdd(&g_sum[cg * 4 + 1], acc.y);
        atomicAdd(&g_sum[cg * 4 + 2], acc.z);
        atomicAdd(&g_sum[cg * 4 + 3], acc.w);
    }
    __syncthreads();
    sh[tid] = s2; __syncthreads();
    if (tid < 16) {
        float4 acc = sh[tid];
        #pragma unroll
        for (int j = 1; j < 16; j++) {
            float4 o = sh[tid + 16 * j];
            acc.x += o.x; acc.y += o.y; acc.z += o.z; acc.w += o.w;
        }
        atomicAdd(&g_sumsq[cg * 4 + 0], acc.x);
        atomicAdd(&g_sumsq[cg * 4 + 1], acc.y);
        atomicAdd(&g_sumsq[cg * 4 + 2], acc.z);
        atomicAdd(&g_sumsq[cg * 4 + 3], acc.w);
    }
    __syncthreads();

    // grid sync: last block releases the flag
    if (tid == 0) {
        __threadfence();
        int o = atomicAdd(&g_count, 1);
        if (o == AB_GRID - 1) atomicExch((int*)&g_flag, 1);
        while (g_flag == 0) __nanosleep(64);
    }
    __syncthreads();
    __threadfence();

    // phase 2: read final sums via L2, apply BN from registers
    float4 sc, sf;
    {
        const float invN = 1.0f / (float)N_NODES;
        float4 su = __ldcg(&((const float4*)g_sum)[cg]);
        float4 sq = __ldcg(&((const float4*)g_sumsq)[cg]);
        float4 g4 = ((const float4*)gamma)[cg];
        float4 be4 = ((const float4*)beta)[cg];
        float mx = su.x * invN, my = su.y * invN, mz = su.z * invN, mw = su.w * invN;
        sc.x = g4.x * rsqrtf(sq.x * invN - mx * mx + BN_EPS);
        sc.y = g4.y * rsqrtf(sq.y * invN - my * my + BN_EPS);
        sc.z = g4.z * rsqrtf(sq.z * invN - mz * mz + BN_EPS);
        sc.w = g4.w * rsqrtf(sq.w * invN - mw * mw + BN_EPS);
        sf.x = be4.x - mx * sc.x;
        sf.y = be4.y - my * sc.y;
        sf.z = be4.z - mz * sc.z;
        sf.w = be4.w - mw * sc.w;
    }
    {
        int i = base;
        #pragma unroll
        for (int j = 0; j < AB_ITERS; j++, i += AB_STRIDE) {
            if (i < total4) {
                float4 v = vals[j];
                v.x = v.x * sc.x + sf.x;
                v.y = v.y * sc.y + sf.y;
                v.z = v.z * sc.z + sf.z;
                v.w = v.w * sc.w + sf.w;
                ((float4*)out)[i] = v;
            }
        }
    }
}

// ---------------- streams/events (created once; no device memory) ----------------
static struct SideStream {
    cudaStream_t s;
    cudaEvent_t fork_ev, join_ev;
    SideStream() {
        cudaStreamCreateWithFlags(&s, cudaStreamNonBlocking);
        cudaEventCreateWithFlags(&fork_ev, cudaEventDisableTiming);
        cudaEventCreateWithFlags(&join_ev, cudaEventDisableTiming);
        cudaFuncSetAttribute(k_gemm, cudaFuncAttributeMaxDynamicSharedMemorySize, SMEM_TOT);
    }
} g_ss;

// ---------------- launch ----------------
extern "C" void kernel_launch(void* const* d_in, const int* in_sizes, int n_in,
                              void* d_out, int out_size) {
    const float*        x     = (const float*)d_in[0];
    const unsigned int* ei    = (const unsigned int*)d_in[1];  // int32 or int64, sniffed
    const float*        W     = (const float*)d_in[2];
    const float*        bias  = (const float*)d_in[3];
    const float*        gamma = (const float*)d_in[4];
    const float*        beta  = (const float*)d_in[5];
    float*              out   = (float*)d_out;

    static bool attr_done = false;
    if (!attr_done) {   // first call is outside graph capture
        cudaFuncSetAttribute(k_gemm, cudaFuncAttributeMaxDynamicSharedMemorySize, SMEM_TOT);
        attr_done = true;
    }

    // fork: edge chain on side stream, overlapped with GEMM on main stream
    cudaEventRecord(g_ss.fork_ev, 0);
    cudaStreamWaitEvent(g_ss.s, g_ss.fork_ev, 0);

    k_init_sniff<<<(N_NODES + 255) / 256, 256, 0, g_ss.s>>>(ei);
    k_decode_deg<<<(2 * N_EDGES + 255) / 256, 256, 0, g_ss.s>>>(ei);
    k_dinv<<<(N_NODES + 255) / 256, 256, 0, g_ss.s>>>();
    cudaEventRecord(g_ss.join_ev, g_ss.s);

    k_gemm<<<(N_NODES + TILE_M - 1) / TILE_M, 256, SMEM_TOT>>>(x, W);

    // join, then scatter + fused act/bn on main stream
    cudaStreamWaitEvent(0, g_ss.join_ev, 0);
    k_scatter<<<(int)(((long long)N_EDGES * 16 + 255) / 256), 256>>>();
    k_act_bn<<<AB_GRID, 256>>>(bias, gamma, beta, out);
}